// round 5
// baseline (speedup 1.0000x reference)
#include <cuda_runtime.h>
#include <cstddef>

// Problem constants
#define BATCH   16
#define IN_CH   2
#define FDIM    2048
#define TDIM    1024
#define NBANDS  64
#define BANDSZ  32      // FDIM / NBANDS
#define EMB     128

#define T_CHUNK 256
#define THREADS 256

__global__ __launch_bounds__(THREADS)
void bandsplit_kernel(const float* __restrict__ x,
                      const float* __restrict__ W,
                      const float* __restrict__ bias,
                      float* __restrict__ out)
{
    const int g  = blockIdx.x;
    const int tc = g & 3;               // t-chunk index (TDIM / T_CHUNK = 4)
    const int n  = (g >> 2) & 63;       // band
    const int b  = g >> 8;              // batch

    const int tid  = threadIdx.x;
    const int lane = tid & 31;
    const int wrp  = tid >> 5;          // warp id in block: 0..7

    // Warp owns 32 consecutive t. Lane split: fg = f-group (4 x 8 rows),
    // c8 = float4 column within the warp's 32-t span.
    const int fg = lane >> 3;           // 0..3
    const int c8 = lane & 7;            // 0..7
    const int t_warp = tc * T_CHUNK + wrp * 32;

    // ---------------- Phase 1: band sum (16 float4 loads/thread) ------------
    // x index: ((b*IN_CH + c)*FDIM + f)*TDIM + t
    const size_t ft   = (size_t)FDIM * TDIM;
    const int    row4 = TDIM / 4;       // float4 per f-row

    const float4* xp0 = (const float4*)(x + (size_t)b * IN_CH * ft
                                          + (size_t)(n * BANDSZ + fg * 8) * TDIM
                                          + t_warp) + c8;
    const float4* xp1 = xp0 + ft / 4;

    float a0[4] = {0.f, 0.f, 0.f, 0.f};
    float a1[4] = {0.f, 0.f, 0.f, 0.f};
    #pragma unroll
    for (int f = 0; f < 8; f++) {
        const float4 v = __ldcs(xp0 + (size_t)f * row4);
        a0[0] += v.x; a0[1] += v.y; a0[2] += v.z; a0[3] += v.w;
    }
    #pragma unroll
    for (int f = 0; f < 8; f++) {
        const float4 v = __ldcs(xp1 + (size_t)f * row4);
        a1[0] += v.x; a1[1] += v.y; a1[2] += v.z; a1[3] += v.w;
    }

    // Cross-f reduction: butterfly over fg (lanes l, l^8, l^16, l^24 share c8).
    #pragma unroll
    for (int k = 0; k < 4; k++) {
        a0[k] += __shfl_xor_sync(0xffffffffu, a0[k], 8);
        a0[k] += __shfl_xor_sync(0xffffffffu, a0[k], 16);
        a1[k] += __shfl_xor_sync(0xffffffffu, a1[k], 8);
        a1[k] += __shfl_xor_sync(0xffffffffu, a1[k], 16);
    }
    // Every lane now holds the full band SUM for its c8 column (both channels).

    // ---------------- Phase 2: project and write (warp-local) ---------------
    // Fold the 1/BANDSZ mean scale into the weights.
    const int e4 = lane * 4;
    const float inv = 1.f / BANDSZ;
    float4 w0 = *(const float4*)(W + ((size_t)n * IN_CH + 0) * EMB + e4);
    float4 w1 = *(const float4*)(W + ((size_t)n * IN_CH + 1) * EMB + e4);
    const float4 bb = *(const float4*)(bias + (size_t)n * EMB + e4);
    w0.x *= inv; w0.y *= inv; w0.z *= inv; w0.w *= inv;
    w1.x *= inv; w1.y *= inv; w1.z *= inv; w1.w *= inv;

    // out index: ((b*NBANDS + n)*TDIM + t)*EMB + e
    float4* op = (float4*)(out + (((size_t)b * NBANDS + n) * TDIM + t_warp) * EMB + e4);

    #pragma unroll
    for (int t = 0; t < 32; t++) {
        const float m0 = __shfl_sync(0xffffffffu, a0[t & 3], t >> 2);
        const float m1 = __shfl_sync(0xffffffffu, a1[t & 3], t >> 2);
        float4 r;
        r.x = fmaf(m0, w0.x, fmaf(m1, w1.x, bb.x));
        r.y = fmaf(m0, w0.y, fmaf(m1, w1.y, bb.y));
        r.z = fmaf(m0, w0.z, fmaf(m1, w1.z, bb.z));
        r.w = fmaf(m0, w0.w, fmaf(m1, w1.w, bb.w));
        __stcs(op + (size_t)t * (EMB / 4), r);
    }
}

extern "C" void kernel_launch(void* const* d_in, const int* in_sizes, int n_in,
                              void* d_out, int out_size)
{
    const float* x    = (const float*)d_in[0];
    const float* W    = (const float*)d_in[1];
    const float* bias = (const float*)d_in[2];
    float* out        = (float*)d_out;

    const int grid = BATCH * NBANDS * (TDIM / T_CHUNK);  // 4096
    bandsplit_kernel<<<grid, THREADS>>>(x, W, bias, out);
}